// round 2
// baseline (speedup 1.0000x reference)
#include <cuda_runtime.h>
#include <cstdint>

#define MAXN 100000
#define MAXE 1600000

// ---------------- static scratch (allocation-free rule) ----------------
__device__ __align__(16) float g_deg[MAXN];
__device__ __align__(16) float g_dinv[MAXN];
__device__ __align__(16) float g_norm[MAXE];
__device__ __align__(16) float g_xw[MAXN * 32];
__device__ __align__(16) float g_agg[MAXN * 32];
__device__ __align__(16) float g_feat[(size_t)MAXN * 192];   // [out1..out5, state]
__device__ __align__(16) float g_h1[(size_t)MAXN * 256];
__device__ __align__(16) float g_h2[(size_t)MAXN * 256];
__device__ __align__(16) float g_conc[MAXN];
__device__ float g_partial[512];
__device__ float g_sum;

// ---------------- f32x2 packed FMA helpers (Blackwell) ----------------
__device__ __forceinline__ unsigned long long pk2(float lo, float hi) {
    unsigned long long r;
    asm("mov.b64 %0, {%1, %2};" : "=l"(r) : "f"(lo), "f"(hi));
    return r;
}
__device__ __forceinline__ void upk2(unsigned long long v, float& lo, float& hi) {
    asm("mov.b64 {%0, %1}, %2;" : "=f"(lo), "=f"(hi) : "l"(v));
}
__device__ __forceinline__ void ffma2(unsigned long long& c, unsigned long long a, unsigned long long b) {
    asm("fma.rn.f32x2 %0, %1, %2, %0;" : "+l"(c) : "l"(a), "l"(b));
}

// ---------------- prep: deg=1 (self loop), zero sum ----------------
__global__ void k_prep(int Nn) {
    int i = blockIdx.x * blockDim.x + threadIdx.x;
    if (i < Nn) g_deg[i] = 1.0f;
    if (i == 0) g_sum = 0.0f;
}

__global__ void k_deg(const int* __restrict__ dst, int E) {
    int e = blockIdx.x * blockDim.x + threadIdx.x;
    if (e < E) atomicAdd(&g_deg[dst[e]], 1.0f);
}

__global__ void k_dinv(int Nn) {
    int i = blockIdx.x * blockDim.x + threadIdx.x;
    if (i < Nn) {
        float d = g_deg[i];
        g_dinv[i] = d > 0.0f ? rsqrtf(d) : 0.0f;
    }
}

__global__ void k_normc(const int* __restrict__ src, const int* __restrict__ dst, int E) {
    int e = blockIdx.x * blockDim.x + threadIdx.x;
    if (e < E) g_norm[e] = g_dinv[src[e]] * g_dinv[dst[e]];
}

// ---------------- per-layer: x (relu?) -> feat store -> xw = xW; agg init = dinv^2*xw + b
// xin == nullptr means read g_agg (previous layer pre-activation)
__global__ void __launch_bounds__(256) k_xw(const float* __restrict__ xin,
                                            const float* __restrict__ W,
                                            const float* __restrict__ b,
                                            int relu_in, int feat_col, int Nn) {
    __shared__ float Ws[32 * 32];
    __shared__ float bs[32];
    int tid = threadIdx.x;
    for (int i = tid; i < 1024; i += 256) Ws[i] = W[i];
    if (tid < 32) bs[tid] = b[tid];
    __syncthreads();

    int lane = tid & 31;
    int w = tid >> 5;
    int node = blockIdx.x * 8 + w;
    if (node >= Nn) return;

    const float* x = xin ? xin : g_agg;
    float v = x[node * 32 + lane];
    if (relu_in) v = fmaxf(v, 0.0f);
    if (feat_col >= 0) g_feat[(size_t)node * 192 + feat_col + lane] = v;

    float acc = 0.0f;
#pragma unroll
    for (int k = 0; k < 32; k++) {
        float xk = __shfl_sync(0xffffffffu, v, k);
        acc = fmaf(xk, Ws[k * 32 + lane], acc);
    }
    g_xw[node * 32 + lane] = acc;
    float di = g_dinv[node];
    g_agg[node * 32 + lane] = di * di * acc + bs[lane];
}

// ---------------- edge scatter: agg[dst] += norm * xw[src], vector atomics ----------------
__global__ void __launch_bounds__(256) k_edge(const int* __restrict__ src,
                                              const int* __restrict__ dst, int E) {
    int t = blockIdx.x * blockDim.x + threadIdx.x;
    int e = t >> 3;
    if (e >= E) return;
    int q = t & 7;
    int s = src[e];
    int d = dst[e];
    float w = g_norm[e];
    const float4* xw4 = (const float4*)g_xw;
    float4 v = xw4[s * 8 + q];
    v.x *= w; v.y *= w; v.z *= w; v.w *= w;
    float* a = g_agg + ((size_t)d * 32 + q * 4);
    unsigned long long ga = (unsigned long long)__cvta_generic_to_global(a);
    asm volatile("red.global.add.v4.f32 [%0], {%1, %2, %3, %4};"
                 :: "l"(ga), "f"(v.x), "f"(v.y), "f"(v.z), "f"(v.w)
                 : "memory");
}

// ---------------- out5 = relu(agg) into feat cols 128..159 ----------------
__global__ void k_relu5(int Nn) {
    int i = blockIdx.x * blockDim.x + threadIdx.x;
    if (i < Nn * 32) {
        int node = i >> 5, lane = i & 31;
        g_feat[(size_t)node * 192 + 128 + lane] = fmaxf(g_agg[i], 0.0f);
    }
}

// ---------------- tiled GEMM + bias + leaky_relu, f32x2 packed FMA ----------------
// SRC: 0 -> A=g_feat (K=192), C=g_h1 ; 1 -> A=g_h1 (K=256), C=g_h2
template <int KTOT, int SRC>
__global__ void __launch_bounds__(256) k_gemm(const float* __restrict__ B,
                                              const float* __restrict__ bias,
                                              int M, int Ncols) {
    const int BM = 128, BN = 64, BK = 32;
    __shared__ float As[BM][BK + 4];
    __shared__ float Bs[BK][BN];

    const float* __restrict__ A = (SRC == 0) ? g_feat : g_h1;
    float* __restrict__ C       = (SRC == 0) ? g_h1   : g_h2;

    int tid = threadIdx.x;
    int tx = tid & 15;   // N micro (16 * 4 = 64)
    int ty = tid >> 4;   // M micro (16 * 8 = 128)
    int m0 = blockIdx.x * BM;
    int n0 = blockIdx.y * BN;

    unsigned long long acc[8][2];
#pragma unroll
    for (int i = 0; i < 8; i++) { acc[i][0] = 0ull; acc[i][1] = 0ull; }

    int ar = tid >> 3;   // 0..31
    int ac = tid & 7;    // float4 col within 32 k
    int br = tid >> 4;   // 0..15
    int bc = tid & 15;   // float4 col within 64 n

    for (int k0 = 0; k0 < KTOT; k0 += BK) {
#pragma unroll
        for (int p = 0; p < 4; p++) {
            int r = ar + p * 32;
            int gm = m0 + r;
            float4 v = make_float4(0.f, 0.f, 0.f, 0.f);
            if (gm < M) v = *(const float4*)(A + (size_t)gm * KTOT + k0 + ac * 4);
            *(float4*)&As[r][ac * 4] = v;
        }
#pragma unroll
        for (int p = 0; p < 2; p++) {
            int r = br + p * 16;
            float4 v = *(const float4*)(B + (size_t)(k0 + r) * Ncols + n0 + bc * 4);
            *(float4*)&Bs[r][bc * 4] = v;
        }
        __syncthreads();
#pragma unroll
        for (int k = 0; k < BK; k++) {
            float4 bv = *(const float4*)&Bs[k][tx * 4];
            unsigned long long b0 = pk2(bv.x, bv.y);
            unsigned long long b1 = pk2(bv.z, bv.w);
#pragma unroll
            for (int i = 0; i < 8; i++) {
                float a = As[ty * 8 + i][k];
                unsigned long long a2 = pk2(a, a);
                ffma2(acc[i][0], a2, b0);
                ffma2(acc[i][1], a2, b1);
            }
        }
        __syncthreads();
    }

#pragma unroll
    for (int i = 0; i < 8; i++) {
        int gm = m0 + ty * 8 + i;
        if (gm >= M) continue;
        float o[4];
        upk2(acc[i][0], o[0], o[1]);
        upk2(acc[i][1], o[2], o[3]);
#pragma unroll
        for (int j = 0; j < 4; j++) {
            int gn = n0 + tx * 4 + j;
            float v = o[j] + bias[gn];
            v = v > 0.0f ? v : 0.01f * v;  // leaky_relu 0.01
            C[(size_t)gm * Ncols + gn] = v;
        }
    }
}

// ---------------- final linear 256->1 + softplus ----------------
__global__ void __launch_bounds__(256) k_lin3(const float* __restrict__ W3,
                                              const float* __restrict__ b3, int Nn) {
    int warp = (blockIdx.x * blockDim.x + threadIdx.x) >> 5;
    int lane = threadIdx.x & 31;
    if (warp >= Nn) return;
    const float* h = g_h2 + (size_t)warp * 256;
    float s = 0.0f;
#pragma unroll
    for (int k = 0; k < 8; k++) s = fmaf(h[lane + 32 * k], W3[lane + 32 * k], s);
#pragma unroll
    for (int o = 16; o; o >>= 1) s += __shfl_xor_sync(0xffffffffu, s, o);
    if (lane == 0) {
        float x = s + b3[0];
        // softplus = logaddexp(x, 0) = max(x,0) + log1p(exp(-|x|))
        g_conc[warp] = fmaxf(x, 0.0f) + log1pf(expf(-fabsf(x)));
    }
}

// ---------------- deterministic two-pass sum ----------------
__global__ void k_reduce1(int Nn) {
    __shared__ float sh[256];
    float s = 0.0f;
    for (int i = blockIdx.x * 256 + threadIdx.x; i < Nn; i += 256 * 512) s += g_conc[i];
    sh[threadIdx.x] = s;
    __syncthreads();
    for (int o = 128; o; o >>= 1) {
        if (threadIdx.x < o) sh[threadIdx.x] += sh[threadIdx.x + o];
        __syncthreads();
    }
    if (threadIdx.x == 0) g_partial[blockIdx.x] = sh[0];
}

__global__ void k_reduce2() {
    __shared__ float sh[512];
    sh[threadIdx.x] = g_partial[threadIdx.x];
    __syncthreads();
    for (int o = 256; o; o >>= 1) {
        if (threadIdx.x < o) sh[threadIdx.x] += sh[threadIdx.x + o];
        __syncthreads();
    }
    if (threadIdx.x == 0) g_sum = sh[0];
}

__global__ void k_final(float* __restrict__ out, int Nn) {
    int i = blockIdx.x * blockDim.x + threadIdx.x;
    if (i < Nn) out[i] = g_conc[i] / (g_sum + 1e-20f);
}

// ---------------- launch ----------------
extern "C" void kernel_launch(void* const* d_in, const int* in_sizes, int n_in,
                              void* d_out, int out_size) {
    const float* state = (const float*)d_in[0];
    const int* ei = (const int*)d_in[1];          // int32 (JAX x64 disabled)
    const float* W1 = (const float*)d_in[2];
    const float* b1 = (const float*)d_in[3];
    const float* W2 = (const float*)d_in[4];
    const float* b2 = (const float*)d_in[5];
    const float* W3 = (const float*)d_in[6];
    const float* b3 = (const float*)d_in[7];
    const float* lW1 = (const float*)d_in[8];
    const float* lb1 = (const float*)d_in[9];
    const float* lW2 = (const float*)d_in[10];
    const float* lb2 = (const float*)d_in[11];
    const float* lW3 = (const float*)d_in[12];
    const float* lb3 = (const float*)d_in[13];

    int Nn = in_sizes[0] / 32;
    int E = in_sizes[1] / 2;
    const int* src = ei;
    const int* dst = ei + E;
    float* out = (float*)d_out;

    int gN = (Nn + 255) / 256;
    int gE = (E + 255) / 256;
    int gX = (Nn + 7) / 8;
    int gEd = (int)(((long long)E * 8 + 255) / 256);

    k_prep<<<gN, 256>>>(Nn);
    k_deg<<<gE, 256>>>(dst, E);
    k_dinv<<<gN, 256>>>(Nn);
    k_normc<<<gE, 256>>>(src, dst, E);

    // layer 1 (input = state, store state to feat cols 160..191)
    k_xw<<<gX, 256>>>(state, W1, b1, 0, 160, Nn);
    k_edge<<<gEd, 256>>>(src, dst, E);
    // layer 2 (input = agg1, store out1 -> cols 0..31)
    k_xw<<<gX, 256>>>(nullptr, W2, b2, 1, 0, Nn);
    k_edge<<<gEd, 256>>>(src, dst, E);
    // layer 3 (store out2 -> cols 32..63)
    k_xw<<<gX, 256>>>(nullptr, W3, b3, 1, 32, Nn);
    k_edge<<<gEd, 256>>>(src, dst, E);
    // layer 4 (conv3 reused; store out3 -> cols 64..95)
    k_xw<<<gX, 256>>>(nullptr, W3, b3, 1, 64, Nn);
    k_edge<<<gEd, 256>>>(src, dst, E);
    // layer 5 (conv3 reused; store out4 -> cols 96..127)
    k_xw<<<gX, 256>>>(nullptr, W3, b3, 1, 96, Nn);
    k_edge<<<gEd, 256>>>(src, dst, E);
    // out5 -> cols 128..159
    k_relu5<<<(Nn * 32 + 255) / 256, 256>>>(Nn);

    dim3 gg((Nn + 127) / 128, 256 / 64);
    k_gemm<192, 0><<<gg, 256>>>(lW1, lb1, Nn, 256);
    k_gemm<256, 1><<<gg, 256>>>(lW2, lb2, Nn, 256);

    k_lin3<<<(Nn * 32 + 255) / 256, 256>>>(lW3, lb3, Nn);
    k_reduce1<<<512, 256>>>(Nn);
    k_reduce2<<<1, 512>>>();
    k_final<<<gN, 256>>>(out, Nn);
}

// round 6
// speedup vs baseline: 1.2322x; 1.2322x over previous
#include <cuda_runtime.h>
#include <cuda_bf16.h>
#include <mma.h>
#include <cstdint>

using namespace nvcuda;

#define MAXN 100000
#define MAXE 1600000

// ---------------- static scratch (allocation-free rule) ----------------
__device__ __align__(16) float g_deg[MAXN];
__device__ __align__(16) float g_dinv[MAXN];
__device__ __align__(16) float g_norm[MAXE];
__device__ __align__(16) float g_xw[MAXN * 32];
__device__ __align__(16) float g_agg[MAXN * 32];
// bf16 hi/lo planes for MLP inputs (split-precision tensor GEMM)
__device__ __align__(16) __nv_bfloat16 g_fh[(size_t)MAXN * 192];
__device__ __align__(16) __nv_bfloat16 g_fl[(size_t)MAXN * 192];
__device__ __align__(16) __nv_bfloat16 g_h1h[(size_t)MAXN * 256];
__device__ __align__(16) __nv_bfloat16 g_h1l[(size_t)MAXN * 256];
__device__ __align__(16) float g_h2[(size_t)MAXN * 256];
// weights transposed to [N][K] bf16 hi/lo
__device__ __align__(16) __nv_bfloat16 g_B1h[192 * 256];
__device__ __align__(16) __nv_bfloat16 g_B1l[192 * 256];
__device__ __align__(16) __nv_bfloat16 g_B2h[256 * 256];
__device__ __align__(16) __nv_bfloat16 g_B2l[256 * 256];
__device__ __align__(16) float g_conc[MAXN];
__device__ float g_partial[512];
__device__ float g_sum;

// bf16 hi/lo split
__device__ __forceinline__ void bsplit(float v, __nv_bfloat16& h, __nv_bfloat16& l) {
    h = __float2bfloat16(v);
    l = __float2bfloat16(v - __bfloat162float(h));
}

// ---------------- graph prep ----------------
__global__ void k_prep(int Nn) {
    int i = blockIdx.x * blockDim.x + threadIdx.x;
    if (i < Nn) g_deg[i] = 1.0f;
    if (i == 0) g_sum = 0.0f;
}
__global__ void k_deg(const int* __restrict__ dst, int E) {
    int e = blockIdx.x * blockDim.x + threadIdx.x;
    if (e < E) atomicAdd(&g_deg[dst[e]], 1.0f);
}
__global__ void k_dinv(int Nn) {
    int i = blockIdx.x * blockDim.x + threadIdx.x;
    if (i < Nn) {
        float d = g_deg[i];
        g_dinv[i] = d > 0.0f ? rsqrtf(d) : 0.0f;
    }
}
__global__ void k_normc(const int* __restrict__ src, const int* __restrict__ dst, int E) {
    int e = blockIdx.x * blockDim.x + threadIdx.x;
    if (e < E) g_norm[e] = g_dinv[src[e]] * g_dinv[dst[e]];
}

// ---------------- per-layer xw + agg init (+ bf16 split feat store) ----------------
__global__ void __launch_bounds__(256) k_xw(const float* __restrict__ xin,
                                            const float* __restrict__ W,
                                            const float* __restrict__ b,
                                            int relu_in, int feat_col, int Nn) {
    __shared__ float Ws[32 * 32];
    __shared__ float bs[32];
    int tid = threadIdx.x;
    for (int i = tid; i < 1024; i += 256) Ws[i] = W[i];
    if (tid < 32) bs[tid] = b[tid];
    __syncthreads();

    int lane = tid & 31;
    int w = tid >> 5;
    int node = blockIdx.x * 8 + w;
    if (node >= Nn) return;

    const float* x = xin ? xin : g_agg;
    float v = x[node * 32 + lane];
    if (relu_in) v = fmaxf(v, 0.0f);
    if (feat_col >= 0) {
        __nv_bfloat16 h, l;
        bsplit(v, h, l);
        size_t o = (size_t)node * 192 + feat_col + lane;
        g_fh[o] = h;
        g_fl[o] = l;
    }

    float acc = 0.0f;
#pragma unroll
    for (int k = 0; k < 32; k++) {
        float xk = __shfl_sync(0xffffffffu, v, k);
        acc = fmaf(xk, Ws[k * 32 + lane], acc);
    }
    g_xw[node * 32 + lane] = acc;
    float di = g_dinv[node];
    g_agg[node * 32 + lane] = di * di * acc + bs[lane];
}

// ---------------- edge scatter with v4 reduce atomics ----------------
__global__ void __launch_bounds__(256) k_edge(const int* __restrict__ src,
                                              const int* __restrict__ dst, int E) {
    int t = blockIdx.x * blockDim.x + threadIdx.x;
    int e = t >> 3;
    if (e >= E) return;
    int q = t & 7;
    int s = src[e];
    int d = dst[e];
    float w = g_norm[e];
    const float4* xw4 = (const float4*)g_xw;
    float4 v = xw4[s * 8 + q];
    v.x *= w; v.y *= w; v.z *= w; v.w *= w;
    float* a = g_agg + ((size_t)d * 32 + q * 4);
    unsigned long long ga = (unsigned long long)__cvta_generic_to_global(a);
    asm volatile("red.global.add.v4.f32 [%0], {%1, %2, %3, %4};"
                 :: "l"(ga), "f"(v.x), "f"(v.y), "f"(v.z), "f"(v.w)
                 : "memory");
}

// ---------------- out5 = relu(agg) -> bf16 split feat cols 128..159 ----------------
__global__ void k_relu5(int Nn) {
    int i = blockIdx.x * blockDim.x + threadIdx.x;
    if (i < Nn * 32) {
        int node = i >> 5, lane = i & 31;
        float v = fmaxf(g_agg[i], 0.0f);
        __nv_bfloat16 h, l;
        bsplit(v, h, l);
        size_t o = (size_t)node * 192 + 128 + lane;
        g_fh[o] = h;
        g_fl[o] = l;
    }
}

// ---------------- weight convert + transpose: W[K][256] -> [N][K] bf16 hi/lo ----
template <int K, int WHICH>
__global__ void k_convB(const float* __restrict__ Wt) {
    int idx = blockIdx.x * blockDim.x + threadIdx.x;
    if (idx >= K * 256) return;
    int k = idx >> 8, n = idx & 255;
    __nv_bfloat16 h, l;
    bsplit(Wt[idx], h, l);
    if (WHICH == 0) { g_B1h[n * K + k] = h; g_B1l[n * K + k] = l; }
    else           { g_B2h[n * K + k] = h; g_B2l[n * K + k] = l; }
}

// ---------------- wmma bf16x3 split GEMM: C[M,256] = A[M,K] * W[K,256] ------------
// CTA tile 128x128, 8 warps (4M x 2N), warp tile 32x64, BK=32.
// SRC 0: A = g_fh/g_fl (K=192), B = g_B1*, out -> h1 bf16 hi/lo (leaky applied)
// SRC 1: A = g_h1h/l  (K=256), B = g_B2*, out -> g_h2 fp32 (leaky applied)
template <int KTOT, int SRC>
__global__ void __launch_bounds__(256) k_gemm_mma(const float* __restrict__ bias, int Nn) {
    extern __shared__ char sm[];
    const int LDT = 40;                     // bf16 tile ld (pad)
    __nv_bfloat16* Ah = (__nv_bfloat16*)(sm);
    __nv_bfloat16* Al = (__nv_bfloat16*)(sm + 10240);
    __nv_bfloat16* Bh = (__nv_bfloat16*)(sm + 20480);
    __nv_bfloat16* Bl = (__nv_bfloat16*)(sm + 30720);

    int tid = threadIdx.x;
    int wid = tid >> 5, lane = tid & 31;
    int wm = wid & 3, wn = wid >> 2;        // 4 x 2 warp grid
    int m0 = blockIdx.x * 128;
    int n0 = blockIdx.y * 128;

    const __nv_bfloat16* gAh = (SRC == 0) ? g_fh : g_h1h;
    const __nv_bfloat16* gAl = (SRC == 0) ? g_fl : g_h1l;
    const __nv_bfloat16* gBh = (SRC == 0) ? g_B1h : g_B2h;
    const __nv_bfloat16* gBl = (SRC == 0) ? g_B1l : g_B2l;

    wmma::fragment<wmma::accumulator, 16, 16, 16, float> acc[2][4];
#pragma unroll
    for (int i = 0; i < 2; i++)
#pragma unroll
        for (int j = 0; j < 4; j++) wmma::fill_fragment(acc[i][j], 0.0f);

    for (int k0 = 0; k0 < KTOT; k0 += 32) {
        // A tiles: 128 rows x 32 k (hi+lo). 1024 ull chunks / 256 thr = 4 each.
#pragma unroll
        for (int u = 0; u < 4; u++) {
            int idx = tid + u * 256;        // 0..1023
            int r = idx >> 3, c = idx & 7;  // row, 4-elem chunk
            int gm = m0 + r;
            unsigned long long vh = 0ull, vl = 0ull;
            if (gm < Nn) {
                vh = *(const unsigned long long*)(gAh + (size_t)gm * KTOT + k0 + c * 4);
                vl = *(const unsigned long long*)(gAl + (size_t)gm * KTOT + k0 + c * 4);
            }
            *(unsigned long long*)(Ah + r * LDT + c * 4) = vh;
            *(unsigned long long*)(Al + r * LDT + c * 4) = vl;
        }
        // B tiles: 128 n-rows x 32 k (hi+lo), from [N][K] layout.
#pragma unroll
        for (int u = 0; u < 4; u++) {
            int idx = tid + u * 256;
            int r = idx >> 3, c = idx & 7;
            int gn = n0 + r;
            unsigned long long vh = *(const unsigned long long*)(gBh + (size_t)gn * KTOT + k0 + c * 4);
            unsigned long long vl = *(const unsigned long long*)(gBl + (size_t)gn * KTOT + k0 + c * 4);
            *(unsigned long long*)(Bh + r * LDT + c * 4) = vh;
            *(unsigned long long*)(Bl + r * LDT + c * 4) = vl;
        }
        __syncthreads();

#pragma unroll
        for (int kk = 0; kk < 2; kk++) {
            wmma::fragment<wmma::matrix_a, 16, 16, 16, __nv_bfloat16, wmma::row_major> fah[2], fal[2];
            wmma::fragment<wmma::matrix_b, 16, 16, 16, __nv_bfloat16, wmma::col_major> fbh[4], fbl[4];
#pragma unroll
            for (int i = 0; i < 2; i++) {
                wmma::load_matrix_sync(fah[i], Ah + (wm * 32 + i * 16) * LDT + kk * 16, LDT);
                wmma::load_matrix_sync(fal[i], Al + (wm * 32 + i * 16) * LDT + kk * 16, LDT);
            }
#pragma unroll
            for (int j = 0; j < 4; j++) {
                wmma::load_matrix_sync(fbh[j], Bh + (wn * 64 + j * 16) * LDT + kk * 16, LDT);
                wmma::load_matrix_sync(fbl[j], Bl + (wn * 64 + j * 16) * LDT + kk * 16, LDT);
            }
#pragma unroll
            for (int i = 0; i < 2; i++)
#pragma unroll
                for (int j = 0; j < 4; j++) {
                    wmma::mma_sync(acc[i][j], fah[i], fbh[j], acc[i][j]);
                    wmma::mma_sync(acc[i][j], fah[i], fbl[j], acc[i][j]);
                    wmma::mma_sync(acc[i][j], fal[i], fbh[j], acc[i][j]);
                }
        }
        __syncthreads();
    }

    // epilogue: stage each 16x16 tile through smem (reuse tile area), apply bias+leaky
    float* stage = (float*)(sm + wid * 1280);   // 16 x 20 floats per warp
    const int LDS_ = 20;
#pragma unroll
    for (int i = 0; i < 2; i++)
#pragma unroll
        for (int j = 0; j < 4; j++) {
            wmma::store_matrix_sync(stage, acc[i][j], LDS_, wmma::mem_row_major);
            __syncwarp();
            int r = lane >> 1;                  // 0..15
            int c0 = (lane & 1) * 8;
            int gm = m0 + wm * 32 + i * 16 + r;
            int gn0 = n0 + wn * 64 + j * 16 + c0;
            if (gm < Nn) {
#pragma unroll
                for (int t = 0; t < 8; t++) {
                    float v = stage[r * LDS_ + c0 + t] + bias[gn0 + t];
                    v = v > 0.0f ? v : 0.01f * v;   // leaky_relu 0.01
                    if (SRC == 0) {
                        __nv_bfloat16 h, l;
                        bsplit(v, h, l);
                        g_h1h[(size_t)gm * 256 + gn0 + t] = h;
                        g_h1l[(size_t)gm * 256 + gn0 + t] = l;
                    } else {
                        g_h2[(size_t)gm * 256 + gn0 + t] = v;
                    }
                }
            }
            __syncwarp();
        }
}

// ---------------- final linear 256->1 + softplus ----------------
__global__ void __launch_bounds__(256) k_lin3(const float* __restrict__ W3,
                                              const float* __restrict__ b3, int Nn) {
    int warp = (blockIdx.x * blockDim.x + threadIdx.x) >> 5;
    int lane = threadIdx.x & 31;
    if (warp >= Nn) return;
    const float* h = g_h2 + (size_t)warp * 256;
    float s = 0.0f;
#pragma unroll
    for (int k = 0; k < 8; k++) s = fmaf(h[lane + 32 * k], W3[lane + 32 * k], s);
#pragma unroll
    for (int o = 16; o; o >>= 1) s += __shfl_xor_sync(0xffffffffu, s, o);
    if (lane == 0) {
        float x = s + b3[0];
        g_conc[warp] = fmaxf(x, 0.0f) + log1pf(expf(-fabsf(x)));
    }
}

// ---------------- deterministic two-pass sum ----------------
__global__ void k_reduce1(int Nn) {
    __shared__ float sh[256];
    float s = 0.0f;
    for (int i = blockIdx.x * 256 + threadIdx.x; i < Nn; i += 256 * 512) s += g_conc[i];
    sh[threadIdx.x] = s;
    __syncthreads();
    for (int o = 128; o; o >>= 1) {
        if (threadIdx.x < o) sh[threadIdx.x] += sh[threadIdx.x + o];
        __syncthreads();
    }
    if (threadIdx.x == 0) g_partial[blockIdx.x] = sh[0];
}
__global__ void k_reduce2() {
    __shared__ float sh[512];
    sh[threadIdx.x] = g_partial[threadIdx.x];
    __syncthreads();
    for (int o = 256; o; o >>= 1) {
        if (threadIdx.x < o) sh[threadIdx.x] += sh[threadIdx.x + o];
        __syncthreads();
    }
    if (threadIdx.x == 0) g_sum = sh[0];
}
__global__ void k_final(float* __restrict__ out, int Nn) {
    int i = blockIdx.x * blockDim.x + threadIdx.x;
    if (i < Nn) out[i] = g_conc[i] / (g_sum + 1e-20f);
}

// ---------------- launch ----------------
extern "C" void kernel_launch(void* const* d_in, const int* in_sizes, int n_in,
                              void* d_out, int out_size) {
    const float* state = (const float*)d_in[0];
    const int* ei = (const int*)d_in[1];
    const float* W1 = (const float*)d_in[2];
    const float* b1 = (const float*)d_in[3];
    const float* W2 = (const float*)d_in[4];
    const float* b2 = (const float*)d_in[5];
    const float* W3 = (const float*)d_in[6];
    const float* b3 = (const float*)d_in[7];
    const float* lW1 = (const float*)d_in[8];
    const float* lb1 = (const float*)d_in[9];
    const float* lW2 = (const float*)d_in[10];
    const float* lb2 = (const float*)d_in[11];
    const float* lW3 = (const float*)d_in[12];
    const float* lb3 = (const float*)d_in[13];

    int Nn = in_sizes[0] / 32;
    int E = in_sizes[1] / 2;
    const int* src = ei;
    const int* dst = ei + E;
    float* out = (float*)d_out;

    int gN = (Nn + 255) / 256;
    int gE = (E + 255) / 256;
    int gX = (Nn + 7) / 8;
    int gEd = (int)(((long long)E * 8 + 255) / 256);
    const int GEMM_SMEM = 40960;

    k_prep<<<gN, 256>>>(Nn);
    k_deg<<<gE, 256>>>(dst, E);
    k_dinv<<<gN, 256>>>(Nn);
    k_normc<<<gE, 256>>>(src, dst, E);
    k_convB<192, 0><<<(192 * 256 + 255) / 256, 256>>>(lW1);
    k_convB<256, 1><<<(256 * 256 + 255) / 256, 256>>>(lW2);

    // layer 1 (input = state; store state -> feat cols 160..191)
    k_xw<<<gX, 256>>>(state, W1, b1, 0, 160, Nn);
    k_edge<<<gEd, 256>>>(src, dst, E);
    // layer 2 (store out1 -> cols 0..31)
    k_xw<<<gX, 256>>>(nullptr, W2, b2, 1, 0, Nn);
    k_edge<<<gEd, 256>>>(src, dst, E);
    // layer 3 (store out2 -> cols 32..63)
    k_xw<<<gX, 256>>>(nullptr, W3, b3, 1, 32, Nn);
    k_edge<<<gEd, 256>>>(src, dst, E);
    // layer 4 (store out3 -> cols 64..95)
    k_xw<<<gX, 256>>>(nullptr, W3, b3, 1, 64, Nn);
    k_edge<<<gEd, 256>>>(src, dst, E);
    // layer 5 (store out4 -> cols 96..127)
    k_xw<<<gX, 256>>>(nullptr, W3, b3, 1, 96, Nn);
    k_edge<<<gEd, 256>>>(src, dst, E);
    // out5 -> cols 128..159
    k_relu5<<<(Nn * 32 + 255) / 256, 256>>>(Nn);

    dim3 gg((Nn + 127) / 128, 2);
    k_gemm_mma<192, 0><<<gg, 256, GEMM_SMEM>>>(lb1, Nn);
    k_gemm_mma<256, 1><<<gg, 256, GEMM_SMEM>>>(lb2, Nn);

    k_lin3<<<(Nn * 32 + 255) / 256, 256>>>(lW3, lb3, Nn);
    k_reduce1<<<512, 256>>>(Nn);
    k_reduce2<<<1, 512>>>();
    k_final<<<gN, 256>>>(out, Nn);
}

// round 10
// speedup vs baseline: 1.3793x; 1.1195x over previous
#include <cuda_runtime.h>
#include <cuda_bf16.h>
#include <mma.h>
#include <cstdint>

using namespace nvcuda;

#define MAXN 100000
#define MAXE 1600000

// ---------------- static scratch (allocation-free rule) ----------------
__device__ __align__(16) int   g_cnt[MAXN];      // in-degree (excl. self loop)
__device__ __align__(16) int   g_cur[MAXN];      // fill cursors
__device__ __align__(16) int   g_rowptr[MAXN];   // CSR row starts
__device__ __align__(16) int   g_bsum[512];      // block sums for scan
__device__ __align__(16) float g_dinv[MAXN];
__device__ __align__(16) int2  g_csr[MAXE];      // (src, bitcast norm)
__device__ __align__(16) float g_xwA[MAXN * 32];
__device__ __align__(16) float g_xwB[MAXN * 32];
// bf16 hi/lo planes for MLP inputs (split-precision tensor GEMM)
__device__ __align__(16) __nv_bfloat16 g_fh[(size_t)MAXN * 192];
__device__ __align__(16) __nv_bfloat16 g_fl[(size_t)MAXN * 192];
__device__ __align__(16) __nv_bfloat16 g_h1h[(size_t)MAXN * 256];
__device__ __align__(16) __nv_bfloat16 g_h1l[(size_t)MAXN * 256];
__device__ __align__(16) float g_h2[(size_t)MAXN * 256];
// weights transposed to [N][K] bf16 hi/lo
__device__ __align__(16) __nv_bfloat16 g_B1h[192 * 256];
__device__ __align__(16) __nv_bfloat16 g_B1l[192 * 256];
__device__ __align__(16) __nv_bfloat16 g_B2h[256 * 256];
__device__ __align__(16) __nv_bfloat16 g_B2l[256 * 256];
__device__ __align__(16) float g_conc[MAXN];
__device__ float g_partial[512];
__device__ float g_sum;

// bf16 hi/lo split
__device__ __forceinline__ void bsplit(float v, __nv_bfloat16& h, __nv_bfloat16& l) {
    h = __float2bfloat16(v);
    l = __float2bfloat16(v - __bfloat162float(h));
}

// ---------------- CSR build ----------------
__global__ void __launch_bounds__(256) k_prep(int Nn) {
    int i = blockIdx.x * blockDim.x + threadIdx.x;
    if (i < Nn) { g_cnt[i] = 0; g_cur[i] = 0; }
    if (i == 0) g_sum = 0.0f;
}
__global__ void __launch_bounds__(256) k_cnt(const int* __restrict__ dst, int E) {
    int e = blockIdx.x * blockDim.x + threadIdx.x;
    if (e < E) atomicAdd(&g_cnt[dst[e]], 1);
}
// per-block sums of g_cnt (256 per block)
__global__ void __launch_bounds__(256) k_scanA(int Nn) {
    __shared__ int sh[256];
    int i = blockIdx.x * 256 + threadIdx.x;
    sh[threadIdx.x] = (i < Nn) ? g_cnt[i] : 0;
    __syncthreads();
    for (int o = 128; o; o >>= 1) {
        if (threadIdx.x < o) sh[threadIdx.x] += sh[threadIdx.x + o];
        __syncthreads();
    }
    if (threadIdx.x == 0) g_bsum[blockIdx.x] = sh[0];
}
// exclusive scan of block sums (nb <= 512), one block of 512
__global__ void __launch_bounds__(512) k_scanB(int nb) {
    __shared__ int sh[512];
    int t = threadIdx.x;
    int v = (t < nb) ? g_bsum[t] : 0;
    sh[t] = v;
    __syncthreads();
    for (int o = 1; o < 512; o <<= 1) {
        int x = (t >= o) ? sh[t - o] : 0;
        __syncthreads();
        sh[t] += x;
        __syncthreads();
    }
    if (t < nb) g_bsum[t] = sh[t] - v;   // exclusive
}
// local exclusive scan + block offset -> rowptr; also dinv
__global__ void __launch_bounds__(256) k_scanC(int Nn) {
    __shared__ int sh[256];
    int i = blockIdx.x * 256 + threadIdx.x;
    int t = threadIdx.x;
    int v = (i < Nn) ? g_cnt[i] : 0;
    sh[t] = v;
    __syncthreads();
    for (int o = 1; o < 256; o <<= 1) {
        int x = (t >= o) ? sh[t - o] : 0;
        __syncthreads();
        sh[t] += x;
        __syncthreads();
    }
    if (i < Nn) {
        g_rowptr[i] = g_bsum[blockIdx.x] + sh[t] - v;
        g_dinv[i] = rsqrtf((float)(v + 1));   // + self loop
    }
}
__global__ void __launch_bounds__(256) k_fill(const int* __restrict__ src,
                                              const int* __restrict__ dst, int E) {
    int e = blockIdx.x * blockDim.x + threadIdx.x;
    if (e >= E) return;
    int s = src[e], d = dst[e];
    int pos = g_rowptr[d] + atomicAdd(&g_cur[d], 1);
    float w = g_dinv[s] * g_dinv[d];
    g_csr[pos] = make_int2(s, __float_as_int(w));
}

// ---------------- layer 1 front: xw1 = state @ W1; store state -> feat 160..191 ----
__global__ void __launch_bounds__(256) k_xw0(const float* __restrict__ state,
                                             const float* __restrict__ W, int Nn) {
    __shared__ float Ws[1024];
    int tid = threadIdx.x;
    for (int i = tid; i < 1024; i += 256) Ws[i] = W[i];
    __syncthreads();
    int lane = tid & 31;
    int node = blockIdx.x * 8 + (tid >> 5);
    if (node >= Nn) return;
    float v = state[node * 32 + lane];
    __nv_bfloat16 h, l;
    bsplit(v, h, l);
    size_t o = (size_t)node * 192 + 160 + lane;
    g_fh[o] = h;
    g_fl[o] = l;
    float acc = 0.0f;
#pragma unroll
    for (int k = 0; k < 32; k++) {
        float xk = __shfl_sync(0xffffffffu, v, k);
        acc = fmaf(xk, Ws[k * 32 + lane], acc);
    }
    g_xwA[node * 32 + lane] = acc;
}

// ---------------- fused pull layer: agg -> relu -> feat store -> next xw ----------
// PP=0: in g_xwA, out g_xwB ; PP=1: in g_xwB, out g_xwA
// (xw buffers selected INSIDE the kernel — device globals must never be passed
//  as kernel args from host code)
template <int FCOL, int HASNEXT, int PP>
__global__ void __launch_bounds__(256) k_pull(const float* __restrict__ b_cur,
                                              const float* __restrict__ Wnext, int Nn) {
    const float* __restrict__ xw_in = PP ? g_xwB : g_xwA;
    float* __restrict__ xw_out      = PP ? g_xwA : g_xwB;
    __shared__ float Ws[1024];
    int tid = threadIdx.x;
    if (HASNEXT) {
        for (int i = tid; i < 1024; i += 256) Ws[i] = Wnext[i];
        __syncthreads();
    }
    int lane = tid & 31;
    int node = blockIdx.x * 8 + (tid >> 5);
    if (node >= Nn) return;

    float di = g_dinv[node];
    float acc = di * di * xw_in[node * 32 + lane] + b_cur[lane];
    int start = g_rowptr[node];
    int cnt = g_cnt[node];
    for (int e = 0; e < cnt; e++) {
        int2 p = g_csr[start + e];
        acc = fmaf(__int_as_float(p.y), xw_in[(size_t)p.x * 32 + lane], acc);
    }
    float v = fmaxf(acc, 0.0f);
    __nv_bfloat16 h, l;
    bsplit(v, h, l);
    size_t o = (size_t)node * 192 + FCOL + lane;
    g_fh[o] = h;
    g_fl[o] = l;
    if (HASNEXT) {
        float a2 = 0.0f;
#pragma unroll
        for (int k = 0; k < 32; k++) {
            float xk = __shfl_sync(0xffffffffu, v, k);
            a2 = fmaf(xk, Ws[k * 32 + lane], a2);
        }
        xw_out[node * 32 + lane] = a2;
    }
}

// ---------------- weight convert + transpose: W[K][256] -> [N][K] bf16 hi/lo ----
template <int K, int WHICH>
__global__ void __launch_bounds__(256) k_convB(const float* __restrict__ Wt) {
    int idx = blockIdx.x * blockDim.x + threadIdx.x;
    if (idx >= K * 256) return;
    int k = idx >> 8, n = idx & 255;
    __nv_bfloat16 h, l;
    bsplit(Wt[idx], h, l);
    if (WHICH == 0) { g_B1h[n * K + k] = h; g_B1l[n * K + k] = l; }
    else           { g_B2h[n * K + k] = h; g_B2l[n * K + k] = l; }
}

// ---------------- wmma bf16x3 split GEMM (identical to R6 pass) ----------------
template <int KTOT, int SRC>
__global__ void __launch_bounds__(256) k_gemm_mma(const float* __restrict__ bias, int Nn) {
    extern __shared__ char sm[];
    const int LDT = 40;
    __nv_bfloat16* Ah = (__nv_bfloat16*)(sm);
    __nv_bfloat16* Al = (__nv_bfloat16*)(sm + 10240);
    __nv_bfloat16* Bh = (__nv_bfloat16*)(sm + 20480);
    __nv_bfloat16* Bl = (__nv_bfloat16*)(sm + 30720);

    int tid = threadIdx.x;
    int wid = tid >> 5, lane = tid & 31;
    int wm = wid & 3, wn = wid >> 2;
    int m0 = blockIdx.x * 128;
    int n0 = blockIdx.y * 128;

    const __nv_bfloat16* gAh = (SRC == 0) ? g_fh : g_h1h;
    const __nv_bfloat16* gAl = (SRC == 0) ? g_fl : g_h1l;
    const __nv_bfloat16* gBh = (SRC == 0) ? g_B1h : g_B2h;
    const __nv_bfloat16* gBl = (SRC == 0) ? g_B1l : g_B2l;

    wmma::fragment<wmma::accumulator, 16, 16, 16, float> acc[2][4];
#pragma unroll
    for (int i = 0; i < 2; i++)
#pragma unroll
        for (int j = 0; j < 4; j++) wmma::fill_fragment(acc[i][j], 0.0f);

    for (int k0 = 0; k0 < KTOT; k0 += 32) {
#pragma unroll
        for (int u = 0; u < 4; u++) {
            int idx = tid + u * 256;
            int r = idx >> 3, c = idx & 7;
            int gm = m0 + r;
            unsigned long long vh = 0ull, vl = 0ull;
            if (gm < Nn) {
                vh = *(const unsigned long long*)(gAh + (size_t)gm * KTOT + k0 + c * 4);
                vl = *(const unsigned long long*)(gAl + (size_t)gm * KTOT + k0 + c * 4);
            }
            *(unsigned long long*)(Ah + r * LDT + c * 4) = vh;
            *(unsigned long long*)(Al + r * LDT + c * 4) = vl;
        }
#pragma unroll
        for (int u = 0; u < 4; u++) {
            int idx = tid + u * 256;
            int r = idx >> 3, c = idx & 7;
            int gn = n0 + r;
            unsigned long long vh = *(const unsigned long long*)(gBh + (size_t)gn * KTOT + k0 + c * 4);
            unsigned long long vl = *(const unsigned long long*)(gBl + (size_t)gn * KTOT + k0 + c * 4);
            *(unsigned long long*)(Bh + r * LDT + c * 4) = vh;
            *(unsigned long long*)(Bl + r * LDT + c * 4) = vl;
        }
        __syncthreads();

#pragma unroll
        for (int kk = 0; kk < 2; kk++) {
            wmma::fragment<wmma::matrix_a, 16, 16, 16, __nv_bfloat16, wmma::row_major> fah[2], fal[2];
            wmma::fragment<wmma::matrix_b, 16, 16, 16, __nv_bfloat16, wmma::col_major> fbh[4], fbl[4];
#pragma unroll
            for (int i = 0; i < 2; i++) {
                wmma::load_matrix_sync(fah[i], Ah + (wm * 32 + i * 16) * LDT + kk * 16, LDT);
                wmma::load_matrix_sync(fal[i], Al + (wm * 32 + i * 16) * LDT + kk * 16, LDT);
            }
#pragma unroll
            for (int j = 0; j < 4; j++) {
                wmma::load_matrix_sync(fbh[j], Bh + (wn * 64 + j * 16) * LDT + kk * 16, LDT);
                wmma::load_matrix_sync(fbl[j], Bl + (wn * 64 + j * 16) * LDT + kk * 16, LDT);
            }
#pragma unroll
            for (int i = 0; i < 2; i++)
#pragma unroll
                for (int j = 0; j < 4; j++) {
                    wmma::mma_sync(acc[i][j], fah[i], fbh[j], acc[i][j]);
                    wmma::mma_sync(acc[i][j], fah[i], fbl[j], acc[i][j]);
                    wmma::mma_sync(acc[i][j], fal[i], fbh[j], acc[i][j]);
                }
        }
        __syncthreads();
    }

    float* stage = (float*)(sm + wid * 1280);
    const int LDS_ = 20;
#pragma unroll
    for (int i = 0; i < 2; i++)
#pragma unroll
        for (int j = 0; j < 4; j++) {
            wmma::store_matrix_sync(stage, acc[i][j], LDS_, wmma::mem_row_major);
            __syncwarp();
            int r = lane >> 1;
            int c0 = (lane & 1) * 8;
            int gm = m0 + wm * 32 + i * 16 + r;
            int gn0 = n0 + wn * 64 + j * 16 + c0;
            if (gm < Nn) {
#pragma unroll
                for (int t = 0; t < 8; t++) {
                    float v = stage[r * LDS_ + c0 + t] + bias[gn0 + t];
                    v = v > 0.0f ? v : 0.01f * v;
                    if (SRC == 0) {
                        __nv_bfloat16 h, l;
                        bsplit(v, h, l);
                        g_h1h[(size_t)gm * 256 + gn0 + t] = h;
                        g_h1l[(size_t)gm * 256 + gn0 + t] = l;
                    } else {
                        g_h2[(size_t)gm * 256 + gn0 + t] = v;
                    }
                }
            }
            __syncwarp();
        }
}

// ---------------- final linear 256->1 + softplus ----------------
__global__ void __launch_bounds__(256) k_lin3(const float* __restrict__ W3,
                                              const float* __restrict__ b3, int Nn) {
    int warp = (blockIdx.x * blockDim.x + threadIdx.x) >> 5;
    int lane = threadIdx.x & 31;
    if (warp >= Nn) return;
    const float* h = g_h2 + (size_t)warp * 256;
    float s = 0.0f;
#pragma unroll
    for (int k = 0; k < 8; k++) s = fmaf(h[lane + 32 * k], W3[lane + 32 * k], s);
#pragma unroll
    for (int o = 16; o; o >>= 1) s += __shfl_xor_sync(0xffffffffu, s, o);
    if (lane == 0) {
        float x = s + b3[0];
        g_conc[warp] = fmaxf(x, 0.0f) + log1pf(expf(-fabsf(x)));
    }
}

// ---------------- deterministic two-pass sum ----------------
__global__ void __launch_bounds__(256) k_reduce1(int Nn) {
    __shared__ float sh[256];
    float s = 0.0f;
    for (int i = blockIdx.x * 256 + threadIdx.x; i < Nn; i += 256 * 512) s += g_conc[i];
    sh[threadIdx.x] = s;
    __syncthreads();
    for (int o = 128; o; o >>= 1) {
        if (threadIdx.x < o) sh[threadIdx.x] += sh[threadIdx.x + o];
        __syncthreads();
    }
    if (threadIdx.x == 0) g_partial[blockIdx.x] = sh[0];
}
__global__ void __launch_bounds__(512) k_reduce2() {
    __shared__ float sh[512];
    sh[threadIdx.x] = g_partial[threadIdx.x];
    __syncthreads();
    for (int o = 256; o; o >>= 1) {
        if (threadIdx.x < o) sh[threadIdx.x] += sh[threadIdx.x + o];
        __syncthreads();
    }
    if (threadIdx.x == 0) g_sum = sh[0];
}
__global__ void __launch_bounds__(256) k_final(float* __restrict__ out, int Nn) {
    int i = blockIdx.x * blockDim.x + threadIdx.x;
    if (i < Nn) out[i] = g_conc[i] / (g_sum + 1e-20f);
}

// ---------------- launch ----------------
extern "C" void kernel_launch(void* const* d_in, const int* in_sizes, int n_in,
                              void* d_out, int out_size) {
    const float* state = (const float*)d_in[0];
    const int* ei = (const int*)d_in[1];
    const float* W1 = (const float*)d_in[2];
    const float* b1 = (const float*)d_in[3];
    const float* W2 = (const float*)d_in[4];
    const float* b2 = (const float*)d_in[5];
    const float* W3 = (const float*)d_in[6];
    const float* b3 = (const float*)d_in[7];
    const float* lW1 = (const float*)d_in[8];
    const float* lb1 = (const float*)d_in[9];
    const float* lW2 = (const float*)d_in[10];
    const float* lb2 = (const float*)d_in[11];
    const float* lW3 = (const float*)d_in[12];
    const float* lb3 = (const float*)d_in[13];

    int Nn = in_sizes[0] / 32;
    int E = in_sizes[1] / 2;
    const int* src = ei;
    const int* dst = ei + E;
    float* out = (float*)d_out;

    int gN = (Nn + 255) / 256;
    int gE = (E + 255) / 256;
    int gP = (Nn + 7) / 8;
    int nb = (Nn + 255) / 256;
    const int GEMM_SMEM = 40960;

    // CSR build
    k_prep<<<gN, 256>>>(Nn);
    k_cnt<<<gE, 256>>>(dst, E);
    k_scanA<<<nb, 256>>>(Nn);
    k_scanB<<<1, 512>>>(nb);
    k_scanC<<<nb, 256>>>(Nn);
    k_fill<<<gE, 256>>>(src, dst, E);
    k_convB<192, 0><<<(192 * 256 + 255) / 256, 256>>>(lW1);
    k_convB<256, 1><<<(256 * 256 + 255) / 256, 256>>>(lW2);

    // GCN stack: xw0 (writes g_xwA) then 5 fused pulls, ping-pong via template PP
    k_xw0<<<gP, 256>>>(state, W1, Nn);
    k_pull<0,   1, 0><<<gP, 256>>>(b1, W2, Nn);   // in A -> out B
    k_pull<32,  1, 1><<<gP, 256>>>(b2, W3, Nn);   // in B -> out A
    k_pull<64,  1, 0><<<gP, 256>>>(b3, W3, Nn);   // in A -> out B
    k_pull<96,  1, 1><<<gP, 256>>>(b3, W3, Nn);   // in B -> out A
    k_pull<128, 0, 0><<<gP, 256>>>(b3, W3, Nn);   // in A (no next)

    dim3 gg((Nn + 127) / 128, 2);
    k_gemm_mma<192, 0><<<gg, 256, GEMM_SMEM>>>(lb1, Nn);
    k_gemm_mma<256, 1><<<gg, 256, GEMM_SMEM>>>(lb2, Nn);

    k_lin3<<<(Nn * 32 + 255) / 256, 256>>>(lW3, lb3, Nn);
    k_reduce1<<<512, 256>>>(Nn);
    k_reduce2<<<1, 512>>>();
    k_final<<<gN, 256>>>(out, Nn);
}